// round 8
// baseline (speedup 1.0000x reference)
#include <cuda_runtime.h>
#include <cuda_fp16.h>
#include <cstdint>

// Problem constants
constexpr int Bb  = 2;
constexpr int Ss  = 2048;
constexpr int HID = 1024;
constexpr int Hh  = 16;
constexpr int Dd  = 64;
constexpr int Mm  = Bb * Ss;                       // 4096 tokens
constexpr float QC = 0.125f * 1.44269504088896340736f;  // SCALE * log2(e)

// Scratch (static device globals; no allocation allowed)
__device__ __half g_Xh [Mm * HID];       // X in f16, [token][1024]
__device__ __half g_Qh [Mm * HID];       // Q*QC in f16, [token][h*64+d]
__device__ __half g_Kh [Mm * Dd];        // K f16, [token][64]
__device__ __half g_VT [Bb * Dd * Ss];   // V f16 transposed, [b][d][s]
__device__ __half g_AOh[Mm * HID];       // attention out f16, [token][h*64+d]
__device__ __half g_Wt [1152 * HID];     // [Wq*QC | Wk | Wv] transposed: [n][k]
__device__ __half g_Wot[HID * HID];      // Wo transposed: [n][k]

// ---------------------------------------------------------------------------
// Helpers
// ---------------------------------------------------------------------------
__device__ __forceinline__ uint32_t smem_u32(const void* p) {
    return (uint32_t)__cvta_generic_to_shared(p);
}
__device__ __forceinline__ uint32_t h2u(__half2 h) {
    return *reinterpret_cast<uint32_t*>(&h);
}

__device__ __forceinline__ void ldsm4(uint32_t& r0, uint32_t& r1,
                                      uint32_t& r2, uint32_t& r3, uint32_t a) {
    asm volatile("ldmatrix.sync.aligned.m8n8.x4.shared.b16 {%0,%1,%2,%3}, [%4];"
                 : "=r"(r0), "=r"(r1), "=r"(r2), "=r"(r3) : "r"(a));
}
__device__ __forceinline__ void ldsm2(uint32_t& r0, uint32_t& r1, uint32_t a) {
    asm volatile("ldmatrix.sync.aligned.m8n8.x2.shared.b16 {%0,%1}, [%2];"
                 : "=r"(r0), "=r"(r1) : "r"(a));
}

__device__ __forceinline__ void mma_f16(float* c,
    uint32_t a0, uint32_t a1, uint32_t a2, uint32_t a3, uint32_t b0, uint32_t b1)
{
    asm volatile(
        "mma.sync.aligned.m16n8k16.row.col.f32.f16.f16.f32 "
        "{%0,%1,%2,%3}, {%4,%5,%6,%7}, {%8,%9}, {%0,%1,%2,%3};"
        : "+f"(c[0]), "+f"(c[1]), "+f"(c[2]), "+f"(c[3])
        : "r"(a0), "r"(a1), "r"(a2), "r"(a3), "r"(b0), "r"(b1));
}

// pack two f32 (already scaled by SCALE*log2e) to f16x2 and take 2^x of both
__device__ __forceinline__ uint32_t pack_e2(float lo, float hi) {
    uint32_t d;
    asm("{\n\t"
        ".reg .b32 p;\n\t"
        "cvt.rn.f16x2.f32 p, %2, %1;\n\t"
        "ex2.approx.f16x2 %0, p;\n\t"
        "}" : "=r"(d) : "f"(lo), "f"(hi));
    return d;
}

// cp.async 16B
__device__ __forceinline__ void cp16(uint32_t dst, const void* src) {
    asm volatile("cp.async.cg.shared.global [%0], [%1], 16;" :: "r"(dst), "l"(src));
}
__device__ __forceinline__ void cp_commit() {
    asm volatile("cp.async.commit_group;" ::: "memory");
}
__device__ __forceinline__ void cp_wait0() {
    asm volatile("cp.async.wait_group 0;" ::: "memory");
}

// ---------------------------------------------------------------------------
// Fused prep: blocks [0,2048) cvt X->f16; [2048,3200) pack Wqkv; [3200,4224) Wo
// ---------------------------------------------------------------------------
__global__ void __launch_bounds__(256)
prep(const float* __restrict__ X, const float* __restrict__ Wq,
     const float* __restrict__ Wk, const float* __restrict__ Wv,
     const float* __restrict__ Wo)
{
    __shared__ float tb[32][33];
    const int bid = blockIdx.x, tid = threadIdx.x;

    if (bid < 2048) {
        int idx = bid * 256 + tid;
        const float4* s = (const float4*)X;
        float4 a = s[2 * idx], b = s[2 * idx + 1];
        uint4 o;
        o.x = h2u(__floats2half2_rn(a.x, a.y));
        o.y = h2u(__floats2half2_rn(a.z, a.w));
        o.z = h2u(__floats2half2_rn(b.x, b.y));
        o.w = h2u(__floats2half2_rn(b.z, b.w));
        ((uint4*)g_Xh)[idx] = o;
        return;
    }

    const int tx = tid & 31, ty = tid >> 5;
    if (bid < 3200) {
        int id = bid - 2048;
        int n0 = (id % 36) * 32, k0 = (id / 36) * 32;
        #pragma unroll
        for (int i = 0; i < 4; ++i) {
            int k = k0 + ty + i * 8;
            float v;
            if (n0 < 1024)      v = Wq[(size_t)k * 1024 + n0 + tx] * QC;
            else if (n0 < 1088) v = Wk[(size_t)k * 64 + (n0 - 1024) + tx];
            else                v = Wv[(size_t)k * 64 + (n0 - 1088) + tx];
            tb[ty + i * 8][tx] = v;
        }
        __syncthreads();
        #pragma unroll
        for (int i = 0; i < 4; ++i) {
            int n = n0 + ty + i * 8;
            g_Wt[(size_t)n * 1024 + k0 + tx] = __float2half(tb[tx][ty + i * 8]);
        }
    } else {
        int id = bid - 3200;
        int n0 = (id & 31) * 32, k0 = (id >> 5) * 32;
        #pragma unroll
        for (int i = 0; i < 4; ++i)
            tb[ty + i * 8][tx] = Wo[(size_t)(k0 + ty + i * 8) * 1024 + n0 + tx];
        __syncthreads();
        #pragma unroll
        for (int i = 0; i < 4; ++i) {
            int n = n0 + ty + i * 8;
            g_Wot[(size_t)n * 1024 + k0 + tx] = __float2half(tb[tx][ty + i * 8]);
        }
    }
}

// ---------------------------------------------------------------------------
// f16 tensor-core GEMM, cp.async double-buffered: C[M,N]=A[M,1024]@Bt[N,1024]^T
// Block 128x128, BK=64 halves, 256 threads = 8 warps (2m x 4n), warp 64x32.
// smem (dynamic, 73728 B): A[2][128*36]w then B[2][128*36]w; stride 36 words.
// MODE 1: A=g_Xh, B=g_Wt (N=1152); epilogue scatters Qh/Kh/VT.
// MODE 0: A=g_AOh, B=g_Wot; epilogue writes f32 Cf.
// ---------------------------------------------------------------------------
constexpr int GEMM_SMEM = 4 * 4608 * 4;   // 73728 B

template<int MODE>
__global__ void __launch_bounds__(256, 2)
gemm_f16k(float* __restrict__ Cf)
{
    extern __shared__ uint32_t dsm[];
    const __half* Ah = MODE ? g_Xh : g_AOh;
    const __half* Bh = MODE ? g_Wt : g_Wot;

    const int tid  = threadIdx.x;
    const int lane = tid & 31;
    const int w    = tid >> 5;
    const int g    = lane >> 2;
    const int t    = lane & 3;
    const int wm   = (w & 1) * 64;
    const int wn   = (w >> 1) * 32;
    const int row0 = blockIdx.y * 128;
    const int col0 = blockIdx.x * 128;
    const int lr   = tid >> 3, lc = tid & 7;

    const uint4* A4 = (const uint4*)Ah;
    const uint4* B4 = (const uint4*)Bh;

    // ldmatrix lane addresses (buffer 0; add 18432 B for buffer 1)
    const int aRow = wm + (lane & 7) + ((lane >> 3) & 1) * 8;
    const int aW   = ((lane >> 4) & 1) * 4;
    uint32_t aAd[4];
    #pragma unroll
    for (int ma = 0; ma < 4; ++ma)
        aAd[ma] = smem_u32(&dsm[(aRow + ma * 16) * 36 + aW]);
    const int bR = (lane & 7) + ((lane >> 4) & 1) * 8;
    const int bW = ((lane >> 3) & 1) * 4;
    uint32_t bAd[2];
    #pragma unroll
    for (int np = 0; np < 2; ++np)
        bAd[np] = smem_u32(&dsm[9216 + (wn + np * 16 + bR) * 36 + bW]);

    // cp.async destinations (buffer 0 bases)
    const uint32_t dA = smem_u32(&dsm[lr * 36 + lc * 4]);
    const uint32_t dB = smem_u32(&dsm[9216 + lr * 36 + lc * 4]);

    auto issue = [&](int kt, int buf) {
        #pragma unroll
        for (int i = 0; i < 4; ++i) {
            cp16(dA + buf * 18432 + i * 4608,
                 A4 + (size_t)(row0 + lr + i * 32) * 128 + kt * 8 + lc);
            cp16(dB + buf * 18432 + i * 4608,
                 B4 + (size_t)(col0 + lr + i * 32) * 128 + kt * 8 + lc);
        }
        cp_commit();
    };

    float acc[4][4][4] = {};
    issue(0, 0);

    for (int kt = 0; kt < 16; ++kt) {
        const int buf = kt & 1;
        const uint32_t bo = buf * 18432;
        cp_wait0();
        __syncthreads();
        if (kt < 15) issue(kt + 1, buf ^ 1);

        #pragma unroll
        for (int ks = 0; ks < 4; ++ks) {
            uint32_t af[4][4], bf[4][2];
            #pragma unroll
            for (int ma = 0; ma < 4; ++ma)
                ldsm4(af[ma][0], af[ma][1], af[ma][2], af[ma][3],
                      aAd[ma] + bo + ks * 32);
            #pragma unroll
            for (int np = 0; np < 2; ++np)
                ldsm4(bf[2 * np][0], bf[2 * np][1], bf[2 * np + 1][0], bf[2 * np + 1][1],
                      bAd[np] + bo + ks * 32);
            #pragma unroll
            for (int ma = 0; ma < 4; ++ma)
                #pragma unroll
                for (int na = 0; na < 4; ++na)
                    mma_f16(acc[ma][na], af[ma][0], af[ma][1], af[ma][2], af[ma][3],
                            bf[na][0], bf[na][1]);
        }
    }

    // Epilogue
    #pragma unroll
    for (int ma = 0; ma < 4; ++ma) {
        const int r0 = row0 + wm + ma * 16 + g;
        #pragma unroll
        for (int na = 0; na < 4; ++na) {
            const int cbase = col0 + wn + na * 8;
            const int c = cbase + 2 * t;
            if (MODE == 0) {
                *(float2*)&Cf[(size_t)r0 * 1024 + c] =
                    make_float2(acc[ma][na][0], acc[ma][na][1]);
                *(float2*)&Cf[(size_t)(r0 + 8) * 1024 + c] =
                    make_float2(acc[ma][na][2], acc[ma][na][3]);
            } else {
                if (cbase < 1024) {
                    *(__half2*)&g_Qh[(size_t)r0 * 1024 + c] =
                        __floats2half2_rn(acc[ma][na][0], acc[ma][na][1]);
                    *(__half2*)&g_Qh[(size_t)(r0 + 8) * 1024 + c] =
                        __floats2half2_rn(acc[ma][na][2], acc[ma][na][3]);
                } else if (cbase < 1088) {
                    const int kc = c - 1024;
                    *(__half2*)&g_Kh[(size_t)r0 * 64 + kc] =
                        __floats2half2_rn(acc[ma][na][0], acc[ma][na][1]);
                    *(__half2*)&g_Kh[(size_t)(r0 + 8) * 64 + kc] =
                        __floats2half2_rn(acc[ma][na][2], acc[ma][na][3]);
                } else {
                    const int d = c - 1088;
                    const int bz = r0 >> 11, s = r0 & 2047;
                    g_VT[(size_t)(bz * 64 + d)     * 2048 + s]     = __float2half(acc[ma][na][0]);
                    g_VT[(size_t)(bz * 64 + d + 1) * 2048 + s]     = __float2half(acc[ma][na][1]);
                    g_VT[(size_t)(bz * 64 + d)     * 2048 + s + 8] = __float2half(acc[ma][na][2]);
                    g_VT[(size_t)(bz * 64 + d + 1) * 2048 + s + 8] = __float2half(acc[ma][na][3]);
                }
            }
        }
    }
}

// ---------------------------------------------------------------------------
// Flash MQA, f16 mma, cp.async double-buffered K/V, Q-frags hoisted.
// Block = (b, h, 128-q tile), 8 warps x 16 q rows; KV tile = 64 tokens.
// smem (dynamic, 56448 B) words: Q[0,4608) K[4608,+2*2304) V[9216,+2*2304)
// ones[13824,14112). exp via cvt+ex2.f16x2; l via ones-rows in the PV MMA.
// ---------------------------------------------------------------------------
constexpr int FL_SMEM = 14112 * 4;   // 56448 B

__global__ void __launch_bounds__(256, 2) mqa_flash()
{
    extern __shared__ uint32_t dsm[];

    const int tid  = threadIdx.x;
    const int lane = tid & 31;
    const int w    = tid >> 5;
    const int g    = lane >> 2;
    const int t    = lane & 3;
    const int b    = blockIdx.z;
    const int h    = blockIdx.y;
    const int q0   = blockIdx.x * 128;
    const int m0   = w * 16;
    const int lr   = tid >> 3, lc = tid & 7;

    // Q tile load (f16, vectorized)
    const uint4* Q4 = (const uint4*)g_Qh;
    #pragma unroll
    for (int i = 0; i < 4; ++i) {
        int r = lr + i * 32;
        *(uint4*)&dsm[r * 36 + lc * 4] =
            Q4[(size_t)(b * Ss + q0 + r) * 128 + h * 8 + lc];
    }
    // ones rows (l accumulator columns)
    for (int i = tid; i < 288; i += 256) dsm[13824 + i] = 0x3C003C00u;

    // ldmatrix lane addresses
    const int aRow = m0 + (lane & 7) + ((lane >> 3) & 1) * 8;
    const uint32_t qAd = smem_u32(&dsm[aRow * 36 + ((lane >> 4) & 1) * 4]);
    const int bR = (lane & 7) + ((lane >> 4) & 1) * 8;
    const int bW = ((lane >> 3) & 1) * 4;
    uint32_t kAd[4], vAd[4];
    #pragma unroll
    for (int np = 0; np < 4; ++np) {
        kAd[np] = smem_u32(&dsm[4608 + (np * 16 + bR) * 36 + bW]);
        vAd[np] = smem_u32(&dsm[9216 + (np * 16 + bR) * 36 + bW]);
    }
    const uint32_t oAd = smem_u32(&dsm[13824 + (lane & 7) * 36 + bW]);

    const uint4* K4 = (const uint4*)g_Kh;   // 8 uint4 per token row
    const uint4* V4 = (const uint4*)g_VT;   // 256 uint4 per d row
    const uint32_t dK = smem_u32(&dsm[4608 + lr * 36 + lc * 4]);
    const uint32_t dV = smem_u32(&dsm[9216 + lr * 36 + lc * 4]);

    auto issue = [&](int kt, int buf) {
        #pragma unroll
        for (int i = 0; i < 2; ++i) {
            int r = lr + i * 32;
            cp16(dK + buf * 9216 + i * 4608,
                 K4 + (size_t)(b * Ss + kt + r) * 8 + lc);
            cp16(dV + buf * 9216 + i * 4608,
                 V4 + (size_t)(b * 64 + r) * 256 + (kt >> 3) + lc);
        }
        cp_commit();
    };

    issue(0, 0);
    __syncthreads();   // Q + ones visible

    // Hoist loop-invariant Q fragments
    uint32_t qf[4][4];
    #pragma unroll
    for (int ks = 0; ks < 4; ++ks)
        ldsm4(qf[ks][0], qf[ks][1], qf[ks][2], qf[ks][3], qAd + ks * 32);

    float oacc[9][4] = {};

    for (int it = 0; it < 32; ++it) {
        const int buf = it & 1;
        const uint32_t bo = buf * 9216;
        cp_wait0();
        __syncthreads();
        if (it < 31) issue((it + 1) * 64, buf ^ 1);

        // ---- S = Q K^T ----
        float sc[8][4] = {};
        #pragma unroll
        for (int ks = 0; ks < 4; ++ks) {
            #pragma unroll
            for (int np = 0; np < 4; ++np) {
                uint32_t b00, b01, b10, b11;
                ldsm4(b00, b01, b10, b11, kAd[np] + bo + ks * 32);
                mma_f16(sc[2 * np],     qf[ks][0], qf[ks][1], qf[ks][2], qf[ks][3], b00, b01);
                mma_f16(sc[2 * np + 1], qf[ks][0], qf[ks][1], qf[ks][2], qf[ks][3], b10, b11);
            }
        }

        // ---- P = 2^S packed f16x2 ----
        uint32_t pr[8][2];
        #pragma unroll
        for (int na = 0; na < 8; ++na) {
            pr[na][0] = pack_e2(sc[na][0], sc[na][1]);
            pr[na][1] = pack_e2(sc[na][2], sc[na][3]);
        }

        // ---- O += P @ [V | 1] ----
        #pragma unroll
        for (int kp = 0; kp < 4; ++kp) {
            uint32_t A0 = pr[2 * kp][0], A1 = pr[2 * kp][1];
            uint32_t A2 = pr[2 * kp + 1][0], A3 = pr[2 * kp + 1][1];
            #pragma unroll
            for (int np = 0; np < 4; ++np) {
                uint32_t b00, b01, b10, b11;
                ldsm4(b00, b01, b10, b11, vAd[np] + bo + kp * 32);
                mma_f16(oacc[2 * np],     A0, A1, A2, A3, b00, b01);
                mma_f16(oacc[2 * np + 1], A0, A1, A2, A3, b10, b11);
            }
            uint32_t b80, b81;
            ldsm2(b80, b81, oAd + kp * 32);
            mma_f16(oacc[8], A0, A1, A2, A3, b80, b81);
        }
    }

    // Epilogue: normalize by l (aux atom) and write f16 AO
    const float i0 = 1.0f / oacc[8][0];
    const float i1 = 1.0f / oacc[8][2];
    const size_t r0 = (size_t)(b * Ss + q0 + m0 + g) * 1024 + h * 64;
    const size_t r1 = (size_t)(b * Ss + q0 + m0 + g + 8) * 1024 + h * 64;
    #pragma unroll
    for (int nv = 0; nv < 8; ++nv) {
        int c = nv * 8 + 2 * t;
        *(__half2*)&g_AOh[r0 + c] =
            __floats2half2_rn(oacc[nv][0] * i0, oacc[nv][1] * i0);
        *(__half2*)&g_AOh[r1 + c] =
            __floats2half2_rn(oacc[nv][2] * i1, oacc[nv][3] * i1);
    }
}

// ---------------------------------------------------------------------------
// Launch
// ---------------------------------------------------------------------------
extern "C" void kernel_launch(void* const* d_in, const int* in_sizes, int n_in,
                              void* d_out, int out_size)
{
    const float* X  = (const float*)d_in[0];
    const float* Wq = (const float*)d_in[1];
    const float* Wk = (const float*)d_in[2];
    const float* Wv = (const float*)d_in[3];
    const float* Wo = (const float*)d_in[4];
    float* out = (float*)d_out;

    cudaFuncSetAttribute(gemm_f16k<1>,
                         cudaFuncAttributeMaxDynamicSharedMemorySize, GEMM_SMEM);
    cudaFuncSetAttribute(gemm_f16k<0>,
                         cudaFuncAttributeMaxDynamicSharedMemorySize, GEMM_SMEM);
    cudaFuncSetAttribute(mqa_flash,
                         cudaFuncAttributeMaxDynamicSharedMemorySize, FL_SMEM);

    // 1) fused prep: X->f16, weight packs
    prep<<<4224, 256>>>(X, Wq, Wk, Wv, Wo);
    // 2) fused QKV projection: [4096,1152] -> Qh, Kh, VT
    gemm_f16k<1><<<dim3(9, 32), 256, GEMM_SMEM>>>(nullptr);
    // 3) flash attention -> AOh
    mqa_flash<<<dim3(Ss / 128, Hh, Bb), 256, FL_SMEM>>>();
    // 4) out = AOh @ Wo^T (f32 output)
    gemm_f16k<0><<<dim3(8, 32), 256, GEMM_SMEM>>>(out);
}